// round 3
// baseline (speedup 1.0000x reference)
#include <cuda_runtime.h>
#include <cuda_bf16.h>

#define N_NODES 50000
#define N_EDGES 800000
#define N_GRAPHS 128
#define D 128
#define L_LAYERS 4
#define N_CLASSES 10
#define GN_EPS 1e-5f

// ---------------- device scratch (allocation-free rule: __device__ globals) ---
__device__ float g_A[N_NODES * D];     // h
__device__ float g_B[N_NODES * D];     // agg / GIN input
__device__ float g_C[N_NODES * D];     // GEMM1 output
__device__ float g_sum[N_GRAPHS * D];  // per-graph feature sums
__device__ float g_var[N_GRAPHS * D];  // per-graph variance sums
__device__ int   g_cnt[N_GRAPHS];
__device__ float g_cntf[N_GRAPHS];
__device__ float g_gsum[N_GRAPHS * D]; // readout
__device__ float g_m1[N_GRAPHS * D];
__device__ float g_m2[N_GRAPHS * D];
__device__ int   g_edge[2 * N_EDGES];  // canonical int32 edge index
__device__ int   g_batch[N_NODES];     // canonical int32 batch
__device__ int   g_is64;               // dtype flag

// ---------------- dtype detection + index conversion --------------------------
// If the raw buffer holds int64 little-endian values < 2^31, every odd int32
// word is 0. With random values in [0, 50000), 32 consecutive zero odd-words
// from int32 data has probability ~0.
__global__ void detect_k(const int* __restrict__ raw, int* __restrict__ flag) {
    int all0 = 1;
    for (int i = 1; i < 64; i += 2)
        if (raw[i] != 0) all0 = 0;
    *flag = all0;
}

__global__ void conv_k(const int* __restrict__ raw, int* __restrict__ dst, int n,
                       const int* __restrict__ flag) {
    int i = blockIdx.x * blockDim.x + threadIdx.x;
    if (i < n) dst[i] = (*flag) ? raw[2 * i] : raw[i];
}

// ---------------- tiny utility kernels ---------------------------------------
__global__ void copy4_k(const float* __restrict__ s, float* __restrict__ d, int n4) {
    int i = blockIdx.x * blockDim.x + threadIdx.x;
    if (i < n4) reinterpret_cast<float4*>(d)[i] = reinterpret_cast<const float4*>(s)[i];
}

__global__ void zero4_k(float* __restrict__ d, int n4) {
    int i = blockIdx.x * blockDim.x + threadIdx.x;
    if (i < n4) reinterpret_cast<float4*>(d)[i] = make_float4(0.f, 0.f, 0.f, 0.f);
}

__global__ void zero_int_k(int* __restrict__ d, int n) {
    int i = blockIdx.x * blockDim.x + threadIdx.x;
    if (i < n) d[i] = 0;
}

// ---------------- graph counts ------------------------------------------------
__global__ void count_k(const int* __restrict__ batch, int* __restrict__ cnt) {
    __shared__ int bins[N_GRAPHS];
    if (threadIdx.x < N_GRAPHS) bins[threadIdx.x] = 0;
    __syncthreads();
    int i = blockIdx.x * blockDim.x + threadIdx.x;
    if (i < N_NODES) {
        unsigned g = (unsigned)batch[i];
        if (g < N_GRAPHS) atomicAdd(&bins[g], 1);
    }
    __syncthreads();
    if (threadIdx.x < N_GRAPHS) atomicAdd(&cnt[threadIdx.x], bins[threadIdx.x]);
}

__global__ void cntf_k(const int* __restrict__ cnt, float* __restrict__ cntf) {
    int g = threadIdx.x;
    if (g < N_GRAPHS) cntf[g] = fmaxf((float)cnt[g], 1.0f);
}

// ---------------- edge scatter: B[dst] += A[src], vector L2 reductions --------
__global__ void scatter_k(const float* __restrict__ A, float* __restrict__ B,
                          const int* __restrict__ ei) {
    int t = blockIdx.x * blockDim.x + threadIdx.x;
    int e = t >> 5;
    int lane = threadIdx.x & 31;
    if (e >= N_EDGES) return;
    unsigned src = (unsigned)ei[e];
    unsigned dst = (unsigned)ei[N_EDGES + e];
    if (src >= N_NODES || dst >= N_NODES) return;
    const float4 v = *reinterpret_cast<const float4*>(&A[src * D + lane * 4]);
    float* p = &B[dst * D + lane * 4];
    asm volatile("red.global.add.v4.f32 [%0], {%1, %2, %3, %4};"
                 :: "l"(p), "f"(v.x), "f"(v.y), "f"(v.z), "f"(v.w) : "memory");
}

// ---------------- GEMM: out = relu(A[M,128] @ W[128,128] + b) -----------------
// BM=128 rows/block, 256 threads, 8x8 micro-tile per thread, K chunked by 32.
#define BM 128
__global__ void __launch_bounds__(256)
gemm_relu_k(const float* __restrict__ A, const float* __restrict__ W,
            const float* __restrict__ bias, float* __restrict__ outp) {
    __shared__ float sA[BM * 32];
    __shared__ float sW[32 * D];
    int tid = threadIdx.x;
    int r0 = (tid >> 4) * 8;       // 0..120
    int c0 = (tid & 15) * 4;       // 0..60
    int mbase = blockIdx.x * BM;

    float acc[8][8];
#pragma unroll
    for (int r = 0; r < 8; r++)
#pragma unroll
        for (int c = 0; c < 8; c++) acc[r][c] = 0.f;

    for (int kc = 0; kc < D; kc += 32) {
        // load A tile: 128x32 floats = 1024 float4
#pragma unroll
        for (int i = 0; i < 4; i++) {
            int idx = tid + i * 256;
            int rr = idx >> 3;
            int cc = (idx & 7) * 4;
            int grow = mbase + rr;
            float4 v = make_float4(0.f, 0.f, 0.f, 0.f);
            if (grow < N_NODES) v = *reinterpret_cast<const float4*>(&A[grow * D + kc + cc]);
            *reinterpret_cast<float4*>(&sA[rr * 32 + cc]) = v;
        }
        // load W tile: 32x128 floats = 1024 float4
#pragma unroll
        for (int i = 0; i < 4; i++) {
            int idx = tid + i * 256;
            int rr = idx >> 5;
            int cc = (idx & 31) * 4;
            *reinterpret_cast<float4*>(&sW[rr * D + cc]) =
                *reinterpret_cast<const float4*>(&W[(kc + rr) * D + cc]);
        }
        __syncthreads();
#pragma unroll
        for (int k = 0; k < 32; k++) {
            float4 w0 = *reinterpret_cast<float4*>(&sW[k * D + c0]);
            float4 w1 = *reinterpret_cast<float4*>(&sW[k * D + c0 + 64]);
#pragma unroll
            for (int r = 0; r < 8; r++) {
                float a = sA[(r0 + r) * 32 + k];
                acc[r][0] = fmaf(a, w0.x, acc[r][0]);
                acc[r][1] = fmaf(a, w0.y, acc[r][1]);
                acc[r][2] = fmaf(a, w0.z, acc[r][2]);
                acc[r][3] = fmaf(a, w0.w, acc[r][3]);
                acc[r][4] = fmaf(a, w1.x, acc[r][4]);
                acc[r][5] = fmaf(a, w1.y, acc[r][5]);
                acc[r][6] = fmaf(a, w1.z, acc[r][6]);
                acc[r][7] = fmaf(a, w1.w, acc[r][7]);
            }
        }
        __syncthreads();
    }

    float4 b0 = *reinterpret_cast<const float4*>(&bias[c0]);
    float4 b1 = *reinterpret_cast<const float4*>(&bias[c0 + 64]);
#pragma unroll
    for (int r = 0; r < 8; r++) {
        int grow = mbase + r0 + r;
        if (grow < N_NODES) {
            float4 o0, o1;
            o0.x = fmaxf(acc[r][0] + b0.x, 0.f);
            o0.y = fmaxf(acc[r][1] + b0.y, 0.f);
            o0.z = fmaxf(acc[r][2] + b0.z, 0.f);
            o0.w = fmaxf(acc[r][3] + b0.w, 0.f);
            o1.x = fmaxf(acc[r][4] + b1.x, 0.f);
            o1.y = fmaxf(acc[r][5] + b1.y, 0.f);
            o1.z = fmaxf(acc[r][6] + b1.z, 0.f);
            o1.w = fmaxf(acc[r][7] + b1.w, 0.f);
            *reinterpret_cast<float4*>(&outp[grow * D + c0]) = o0;
            *reinterpret_cast<float4*>(&outp[grow * D + c0 + 64]) = o1;
        }
    }
}

// ---------------- segment sum over sorted batch (flush on change) -------------
#define SEG_ROWS 256
__global__ void seg_sum_k(const float* __restrict__ h, const int* __restrict__ batch,
                          float* __restrict__ out) {
    int f = threadIdx.x;
    int r0 = blockIdx.x * SEG_ROWS;
    if (r0 >= N_NODES) return;
    int r1 = min(r0 + SEG_ROWS, N_NODES);
    int gcur = batch[r0] & (N_GRAPHS - 1);
    float acc = 0.f;
    for (int r = r0; r < r1; r++) {
        int g = batch[r] & (N_GRAPHS - 1);
        if (g != gcur) {
            atomicAdd(&out[gcur * D + f], acc);
            acc = 0.f;
            gcur = g;
        }
        acc += h[r * D + f];
    }
    atomicAdd(&out[gcur * D + f], acc);
}

// variance sums: acc += (h - (sum/cnt)*scale)^2, per-graph flushed
__global__ void seg_var_k(const float* __restrict__ h, const int* __restrict__ batch,
                          const float* __restrict__ scale, const float* __restrict__ sum,
                          const float* __restrict__ cntf, float* __restrict__ var) {
    int f = threadIdx.x;
    int r0 = blockIdx.x * SEG_ROWS;
    if (r0 >= N_NODES) return;
    int r1 = min(r0 + SEG_ROWS, N_NODES);
    float sc = scale[f];
    int gcur = batch[r0] & (N_GRAPHS - 1);
    float mean = sum[gcur * D + f] / cntf[gcur] * sc;
    float acc = 0.f;
    for (int r = r0; r < r1; r++) {
        int g = batch[r] & (N_GRAPHS - 1);
        if (g != gcur) {
            atomicAdd(&var[gcur * D + f], acc);
            acc = 0.f;
            gcur = g;
            mean = sum[g * D + f] / cntf[g] * sc;
        }
        float v = h[r * D + f] - mean;
        acc += v * v;
    }
    atomicAdd(&var[gcur * D + f], acc);
}

// normalize + relu, in place
__global__ void norm_k(float* __restrict__ h, const int* __restrict__ batch,
                       const float* __restrict__ sum, const float* __restrict__ var,
                       const float* __restrict__ cntf, const float* __restrict__ weight,
                       const float* __restrict__ bias, const float* __restrict__ scale) {
    int idx = blockIdx.x * blockDim.x + threadIdx.x;
    if (idx >= N_NODES * D) return;
    int r = idx >> 7;
    int f = idx & 127;
    int g = batch[r] & (N_GRAPHS - 1);
    float c = cntf[g];
    float mean = sum[g * D + f] / c * scale[f];
    float vv = var[g * D + f] / c;
    float o = weight[f] * (h[idx] - mean) * rsqrtf(vv + GN_EPS) + bias[f];
    h[idx] = fmaxf(o, 0.f);
}

// ---------------- final MLP ---------------------------------------------------
__global__ void mlp_relu_k(const float* __restrict__ in, const float* __restrict__ W,
                           const float* __restrict__ b, float* __restrict__ outp) {
    __shared__ float row[D];
    int g = blockIdx.x, j = threadIdx.x;
    row[j] = in[g * D + j];
    __syncthreads();
    float acc = b[j];
#pragma unroll
    for (int k = 0; k < D; k++) acc = fmaf(row[k], W[k * D + j], acc);
    outp[g * D + j] = fmaxf(acc, 0.f);
}

__global__ void final_k(const float* __restrict__ in, const float* __restrict__ W,
                        const float* __restrict__ b, float* __restrict__ outp) {
    __shared__ float row[D];
    __shared__ float logits[N_CLASSES];
    __shared__ float red[2];
    int g = blockIdx.x, t = threadIdx.x;
    row[t] = in[g * D + t];
    __syncthreads();
    if (t < N_CLASSES) {
        float acc = b[t];
#pragma unroll
        for (int k = 0; k < D; k++) acc = fmaf(row[k], W[k * N_CLASSES + t], acc);
        logits[t] = acc;
    }
    __syncthreads();
    if (t == 0) {
        float m = -1e30f;
        for (int c = 0; c < N_CLASSES; c++) m = fmaxf(m, logits[c]);
        float s = 0.f;
        for (int c = 0; c < N_CLASSES; c++) s += expf(logits[c] - m);
        red[0] = m;
        red[1] = logf(s);
    }
    __syncthreads();
    if (t < N_CLASSES) outp[g * N_CLASSES + t] = logits[t] - red[0] - red[1];
}

// ---------------- launch ------------------------------------------------------
extern "C" void kernel_launch(void* const* d_in, const int* in_sizes, int n_in,
                              void* d_out, int out_size) {
    const float* x    = (const float*)d_in[0];
    const float* gw1  = (const float*)d_in[1];
    const float* gb1  = (const float*)d_in[2];
    const float* gw2  = (const float*)d_in[3];
    const float* gb2  = (const float*)d_in[4];
    const float* gnw  = (const float*)d_in[5];
    const float* gnb  = (const float*)d_in[6];
    const float* gns  = (const float*)d_in[7];
    const float* fw1  = (const float*)d_in[8];
    const float* fb1  = (const float*)d_in[9];
    const float* fw2  = (const float*)d_in[10];
    const float* fb2  = (const float*)d_in[11];
    const float* fw3  = (const float*)d_in[12];
    const float* fb3  = (const float*)d_in[13];
    const int*   edge_raw  = (const int*)d_in[14];
    const int*   batch_raw = (const int*)d_in[15];
    float* out = (float*)d_out;

    float *A, *B, *C, *SUM, *VAR, *CNTF, *GSUM, *M1, *M2;
    int *CNT, *EDGE, *BATCH, *FLAG;
    cudaGetSymbolAddress((void**)&A, g_A);
    cudaGetSymbolAddress((void**)&B, g_B);
    cudaGetSymbolAddress((void**)&C, g_C);
    cudaGetSymbolAddress((void**)&SUM, g_sum);
    cudaGetSymbolAddress((void**)&VAR, g_var);
    cudaGetSymbolAddress((void**)&CNT, g_cnt);
    cudaGetSymbolAddress((void**)&CNTF, g_cntf);
    cudaGetSymbolAddress((void**)&GSUM, g_gsum);
    cudaGetSymbolAddress((void**)&M1, g_m1);
    cudaGetSymbolAddress((void**)&M2, g_m2);
    cudaGetSymbolAddress((void**)&EDGE, g_edge);
    cudaGetSymbolAddress((void**)&BATCH, g_batch);
    cudaGetSymbolAddress((void**)&FLAG, g_is64);

    const int n4 = N_NODES * D / 4;                 // 1.6M float4
    const int cgrid = (n4 + 255) / 256;
    const int stat4 = N_GRAPHS * D / 4;             // 4096 float4
    const int sgrid = (stat4 + 255) / 256;
    const int seg_blocks = (N_NODES + SEG_ROWS - 1) / SEG_ROWS;
    const int gemm_blocks = (N_NODES + BM - 1) / BM;
    const int scat_blocks = (N_EDGES * 32) / 256;
    const int norm_grid = (N_NODES * D + 255) / 256;

    // canonicalize index dtypes (int64 vs int32, detected at runtime)
    detect_k<<<1, 1>>>(edge_raw, FLAG);
    conv_k<<<(2 * N_EDGES + 255) / 256, 256>>>(edge_raw, EDGE, 2 * N_EDGES, FLAG);
    conv_k<<<(N_NODES + 255) / 256, 256>>>(batch_raw, BATCH, N_NODES, FLAG);

    // h = x
    copy4_k<<<cgrid, 256>>>(x, A, n4);

    // counts (once)
    zero_int_k<<<1, N_GRAPHS>>>(CNT, N_GRAPHS);
    count_k<<<(N_NODES + 255) / 256, 256>>>(BATCH, CNT);
    cntf_k<<<1, N_GRAPHS>>>(CNT, CNTF);

    for (int l = 0; l < L_LAYERS; l++) {
        const float* w1 = gw1 + l * D * D;
        const float* b1 = gb1 + l * D;
        const float* w2 = gw2 + l * D * D;
        const float* b2 = gb2 + l * D;
        const float* nw = gnw + l * D;
        const float* nb = gnb + l * D;
        const float* ns = gns + l * D;

        // B = h; B += sum_{edges} h[src] at dst
        copy4_k<<<cgrid, 256>>>(A, B, n4);
        scatter_k<<<scat_blocks, 256>>>(A, B, EDGE);
        // C = relu(B@W1+b1); A = relu(C@W2+b2)
        gemm_relu_k<<<gemm_blocks, 256>>>(B, w1, b1, C);
        gemm_relu_k<<<gemm_blocks, 256>>>(C, w2, b2, A);
        // GraphNorm + relu in place on A
        zero4_k<<<sgrid, 256>>>(SUM, stat4);
        zero4_k<<<sgrid, 256>>>(VAR, stat4);
        seg_sum_k<<<seg_blocks, D>>>(A, BATCH, SUM);
        seg_var_k<<<seg_blocks, D>>>(A, BATCH, ns, SUM, CNTF, VAR);
        norm_k<<<norm_grid, 256>>>(A, BATCH, SUM, VAR, CNTF, nw, nb, ns);
    }

    // readout + MLP head
    zero4_k<<<sgrid, 256>>>(GSUM, stat4);
    seg_sum_k<<<seg_blocks, D>>>(A, BATCH, GSUM);
    mlp_relu_k<<<N_GRAPHS, D>>>(GSUM, fw1, fb1, M1);
    mlp_relu_k<<<N_GRAPHS, D>>>(M1, fw2, fb2, M2);
    final_k<<<N_GRAPHS, D>>>(M2, fw3, fb3, out);
}

// round 4
// speedup vs baseline: 1.4929x; 1.4929x over previous
#include <cuda_runtime.h>
#include <cuda_bf16.h>

#define N_NODES 50000
#define N_EDGES 800000
#define N_GRAPHS 128
#define D 128
#define L_LAYERS 4
#define N_CLASSES 10
#define GN_EPS 1e-5f

#define SCAN_BLK 1024
#define SCAN_NBLK ((N_NODES + SCAN_BLK - 1) / SCAN_BLK)

// ---------------- device scratch ----------------------------------------------
__device__ float g_A[N_NODES * D];          // h (layer output)
__device__ float g_B[N_NODES * D];          // h + agg (GIN input)
__device__ float g_C[N_NODES * D];          // GEMM1 output
__device__ float g_stats[2 * N_GRAPHS * D]; // [SUM | SUMSQ]
__device__ int   g_cnt[N_GRAPHS];
__device__ float g_cntf[N_GRAPHS];
__device__ float g_gsum[N_GRAPHS * D];
__device__ float g_m1[N_GRAPHS * D];
__device__ float g_m2[N_GRAPHS * D];
__device__ int   g_edge[2 * N_EDGES];       // canonical int32 edge index
__device__ int   g_batch[N_NODES];          // canonical int32 batch
__device__ int   g_is64;
// CSR
__device__ int   g_indeg[N_NODES];
__device__ int   g_rowptr[N_NODES + 1];
__device__ int   g_cursor[N_NODES];
__device__ int   g_col[N_EDGES];
__device__ int   g_blocksum[SCAN_NBLK];
__device__ int   g_blockoff[SCAN_NBLK];

// ---------------- dtype detection + index conversion --------------------------
__global__ void detect_k(const int* __restrict__ raw, int* __restrict__ flag) {
    int all0 = 1;
    for (int i = 1; i < 64; i += 2)
        if (raw[i] != 0) all0 = 0;
    *flag = all0;
}

__global__ void conv_k(const int* __restrict__ raw, int* __restrict__ dst, int n,
                       const int* __restrict__ flag) {
    int i = blockIdx.x * blockDim.x + threadIdx.x;
    if (i < n) dst[i] = (*flag) ? raw[2 * i] : raw[i];
}

// ---------------- tiny utilities ----------------------------------------------
__global__ void zero4_k(float* __restrict__ d, int n4) {
    int i = blockIdx.x * blockDim.x + threadIdx.x;
    if (i < n4) reinterpret_cast<float4*>(d)[i] = make_float4(0.f, 0.f, 0.f, 0.f);
}

__global__ void zero_int_k(int* __restrict__ d, int n) {
    int i = blockIdx.x * blockDim.x + threadIdx.x;
    if (i < n) d[i] = 0;
}

// ---------------- graph counts -------------------------------------------------
__global__ void count_k(const int* __restrict__ batch, int* __restrict__ cnt) {
    __shared__ int bins[N_GRAPHS];
    if (threadIdx.x < N_GRAPHS) bins[threadIdx.x] = 0;
    __syncthreads();
    int i = blockIdx.x * blockDim.x + threadIdx.x;
    if (i < N_NODES) {
        unsigned g = (unsigned)batch[i];
        if (g < N_GRAPHS) atomicAdd(&bins[g], 1);
    }
    __syncthreads();
    if (threadIdx.x < N_GRAPHS) atomicAdd(&cnt[threadIdx.x], bins[threadIdx.x]);
}

__global__ void cntf_k(const int* __restrict__ cnt, float* __restrict__ cntf) {
    int g = threadIdx.x;
    if (g < N_GRAPHS) cntf[g] = fmaxf((float)cnt[g], 1.0f);
}

// ---------------- CSR build ----------------------------------------------------
__global__ void hist_k(const int* __restrict__ ei, int* __restrict__ indeg) {
    int e = blockIdx.x * blockDim.x + threadIdx.x;
    if (e >= N_EDGES) return;
    unsigned dst = (unsigned)ei[N_EDGES + e];
    if (dst < N_NODES) atomicAdd(&indeg[dst], 1);
}

// block-level exclusive scan of indeg chunk; per-block totals out
__global__ void scan1_k(const int* __restrict__ indeg, int* __restrict__ rowptr,
                        int* __restrict__ blocksum) {
    __shared__ int s[SCAN_BLK];
    int t = threadIdx.x;
    int i = blockIdx.x * SCAN_BLK + t;
    int v = (i < N_NODES) ? indeg[i] : 0;
    s[t] = v;
    __syncthreads();
#pragma unroll
    for (int off = 1; off < SCAN_BLK; off <<= 1) {
        int tmp = (t >= off) ? s[t - off] : 0;
        __syncthreads();
        s[t] += tmp;
        __syncthreads();
    }
    if (i < N_NODES) rowptr[i] = s[t] - v;  // exclusive, block-local
    if (t == SCAN_BLK - 1) blocksum[blockIdx.x] = s[t];
}

__global__ void scan2_k(const int* __restrict__ blocksum, int* __restrict__ blockoff,
                        int* __restrict__ rowptr) {
    if (threadIdx.x == 0) {
        int acc = 0;
        for (int b = 0; b < SCAN_NBLK; b++) {
            blockoff[b] = acc;
            acc += blocksum[b];
        }
        rowptr[N_NODES] = acc;
    }
}

__global__ void scan3_k(int* __restrict__ rowptr, int* __restrict__ cursor,
                        const int* __restrict__ blockoff) {
    int i = blockIdx.x * blockDim.x + threadIdx.x;
    if (i < N_NODES) {
        int v = rowptr[i] + blockoff[i / SCAN_BLK];
        rowptr[i] = v;
        cursor[i] = v;
    }
}

__global__ void fill_k(const int* __restrict__ ei, int* __restrict__ cursor,
                       int* __restrict__ col) {
    int e = blockIdx.x * blockDim.x + threadIdx.x;
    if (e >= N_EDGES) return;
    unsigned src = (unsigned)ei[e];
    unsigned dst = (unsigned)ei[N_EDGES + e];
    if (src >= N_NODES || dst >= N_NODES) return;
    int pos = atomicAdd(&cursor[dst], 1);
    col[pos] = (int)src;
}

// ---------------- gather: B[i] = h[i] + sum_{j in N_in(i)} h[j] ---------------
// one warp per node; col loads are warp-uniform (broadcast).
__global__ void __launch_bounds__(256)
gather_k(const float* __restrict__ h, float* __restrict__ B,
         const int* __restrict__ rowptr, const int* __restrict__ col) {
    int gid = (blockIdx.x * blockDim.x + threadIdx.x) >> 5;
    int lane = threadIdx.x & 31;
    if (gid >= N_NODES) return;
    int p0 = rowptr[gid], p1 = rowptr[gid + 1];
    float4 acc = *reinterpret_cast<const float4*>(&h[gid * D + lane * 4]);
    int p = p0;
    // 2-way unrolled broadcast loop for MLP
    for (; p + 1 < p1; p += 2) {
        int s0 = __ldg(&col[p]);
        int s1 = __ldg(&col[p + 1]);
        float4 v0 = *reinterpret_cast<const float4*>(&h[s0 * D + lane * 4]);
        float4 v1 = *reinterpret_cast<const float4*>(&h[s1 * D + lane * 4]);
        acc.x += v0.x + v1.x;
        acc.y += v0.y + v1.y;
        acc.z += v0.z + v1.z;
        acc.w += v0.w + v1.w;
    }
    if (p < p1) {
        int s0 = __ldg(&col[p]);
        float4 v0 = *reinterpret_cast<const float4*>(&h[s0 * D + lane * 4]);
        acc.x += v0.x; acc.y += v0.y; acc.z += v0.z; acc.w += v0.w;
    }
    *reinterpret_cast<float4*>(&B[gid * D + lane * 4]) = acc;
}

// ---------------- GEMM: out = relu(A[M,128] @ W[128,128] + b) -----------------
#define BM 128
__global__ void __launch_bounds__(256)
gemm_relu_k(const float* __restrict__ A, const float* __restrict__ W,
            const float* __restrict__ bias, float* __restrict__ outp) {
    __shared__ float sA[BM * 32];
    __shared__ float sW[32 * D];
    int tid = threadIdx.x;
    int r0 = (tid >> 4) * 8;
    int c0 = (tid & 15) * 4;
    int mbase = blockIdx.x * BM;

    float acc[8][8];
#pragma unroll
    for (int r = 0; r < 8; r++)
#pragma unroll
        for (int c = 0; c < 8; c++) acc[r][c] = 0.f;

    for (int kc = 0; kc < D; kc += 32) {
#pragma unroll
        for (int i = 0; i < 4; i++) {
            int idx = tid + i * 256;
            int rr = idx >> 3;
            int cc = (idx & 7) * 4;
            int grow = mbase + rr;
            float4 v = make_float4(0.f, 0.f, 0.f, 0.f);
            if (grow < N_NODES) v = *reinterpret_cast<const float4*>(&A[grow * D + kc + cc]);
            *reinterpret_cast<float4*>(&sA[rr * 32 + cc]) = v;
        }
#pragma unroll
        for (int i = 0; i < 4; i++) {
            int idx = tid + i * 256;
            int rr = idx >> 5;
            int cc = (idx & 31) * 4;
            *reinterpret_cast<float4*>(&sW[rr * D + cc]) =
                *reinterpret_cast<const float4*>(&W[(kc + rr) * D + cc]);
        }
        __syncthreads();
#pragma unroll
        for (int k = 0; k < 32; k++) {
            float4 w0 = *reinterpret_cast<float4*>(&sW[k * D + c0]);
            float4 w1 = *reinterpret_cast<float4*>(&sW[k * D + c0 + 64]);
#pragma unroll
            for (int r = 0; r < 8; r++) {
                float a = sA[(r0 + r) * 32 + k];
                acc[r][0] = fmaf(a, w0.x, acc[r][0]);
                acc[r][1] = fmaf(a, w0.y, acc[r][1]);
                acc[r][2] = fmaf(a, w0.z, acc[r][2]);
                acc[r][3] = fmaf(a, w0.w, acc[r][3]);
                acc[r][4] = fmaf(a, w1.x, acc[r][4]);
                acc[r][5] = fmaf(a, w1.y, acc[r][5]);
                acc[r][6] = fmaf(a, w1.z, acc[r][6]);
                acc[r][7] = fmaf(a, w1.w, acc[r][7]);
            }
        }
        __syncthreads();
    }

    float4 b0 = *reinterpret_cast<const float4*>(&bias[c0]);
    float4 b1 = *reinterpret_cast<const float4*>(&bias[c0 + 64]);
#pragma unroll
    for (int r = 0; r < 8; r++) {
        int grow = mbase + r0 + r;
        if (grow < N_NODES) {
            float4 o0, o1;
            o0.x = fmaxf(acc[r][0] + b0.x, 0.f);
            o0.y = fmaxf(acc[r][1] + b0.y, 0.f);
            o0.z = fmaxf(acc[r][2] + b0.z, 0.f);
            o0.w = fmaxf(acc[r][3] + b0.w, 0.f);
            o1.x = fmaxf(acc[r][4] + b1.x, 0.f);
            o1.y = fmaxf(acc[r][5] + b1.y, 0.f);
            o1.z = fmaxf(acc[r][6] + b1.z, 0.f);
            o1.w = fmaxf(acc[r][7] + b1.w, 0.f);
            *reinterpret_cast<float4*>(&outp[grow * D + c0]) = o0;
            *reinterpret_cast<float4*>(&outp[grow * D + c0 + 64]) = o1;
        }
    }
}

// ---------------- fused segment stats: SUM(h) and SUM(h^2) --------------------
#define SEG_ROWS 256
__global__ void seg_stats_k(const float* __restrict__ h, const int* __restrict__ batch,
                            float* __restrict__ stats) {
    float* SUM = stats;
    float* SQ = stats + N_GRAPHS * D;
    int f = threadIdx.x;
    int r0 = blockIdx.x * SEG_ROWS;
    if (r0 >= N_NODES) return;
    int r1 = min(r0 + SEG_ROWS, N_NODES);
    int gcur = batch[r0] & (N_GRAPHS - 1);
    float s = 0.f, q = 0.f;
    for (int r = r0; r < r1; r++) {
        int g = batch[r] & (N_GRAPHS - 1);
        if (g != gcur) {
            atomicAdd(&SUM[gcur * D + f], s);
            atomicAdd(&SQ[gcur * D + f], q);
            s = 0.f; q = 0.f;
            gcur = g;
        }
        float v = h[r * D + f];
        s += v;
        q = fmaf(v, v, q);
    }
    atomicAdd(&SUM[gcur * D + f], s);
    atomicAdd(&SQ[gcur * D + f], q);
}

// normalize + relu, in place.  var = Q/c - mean^2 * s * (2 - s)
__global__ void norm_k(float* __restrict__ h, const int* __restrict__ batch,
                       const float* __restrict__ stats, const float* __restrict__ cntf,
                       const float* __restrict__ weight, const float* __restrict__ bias,
                       const float* __restrict__ scale) {
    const float* SUM = stats;
    const float* SQ = stats + N_GRAPHS * D;
    int idx = blockIdx.x * blockDim.x + threadIdx.x;
    if (idx >= N_NODES * D) return;
    int r = idx >> 7;
    int f = idx & 127;
    int g = batch[r] & (N_GRAPHS - 1);
    float c = cntf[g];
    float sc = scale[f];
    float mean = SUM[g * D + f] / c;
    float q = SQ[g * D + f] / c;
    float var = q - mean * mean * sc * (2.f - sc);
    var = fmaxf(var, 0.f);
    float o = weight[f] * (h[idx] - mean * sc) * rsqrtf(var + GN_EPS) + bias[f];
    h[idx] = fmaxf(o, 0.f);
}

// ---------------- readout segment sum ------------------------------------------
__global__ void seg_sum_k(const float* __restrict__ h, const int* __restrict__ batch,
                          float* __restrict__ out) {
    int f = threadIdx.x;
    int r0 = blockIdx.x * SEG_ROWS;
    if (r0 >= N_NODES) return;
    int r1 = min(r0 + SEG_ROWS, N_NODES);
    int gcur = batch[r0] & (N_GRAPHS - 1);
    float acc = 0.f;
    for (int r = r0; r < r1; r++) {
        int g = batch[r] & (N_GRAPHS - 1);
        if (g != gcur) {
            atomicAdd(&out[gcur * D + f], acc);
            acc = 0.f;
            gcur = g;
        }
        acc += h[r * D + f];
    }
    atomicAdd(&out[gcur * D + f], acc);
}

// ---------------- final MLP -----------------------------------------------------
__global__ void mlp_relu_k(const float* __restrict__ in, const float* __restrict__ W,
                           const float* __restrict__ b, float* __restrict__ outp) {
    __shared__ float row[D];
    int g = blockIdx.x, j = threadIdx.x;
    row[j] = in[g * D + j];
    __syncthreads();
    float acc = b[j];
#pragma unroll
    for (int k = 0; k < D; k++) acc = fmaf(row[k], W[k * D + j], acc);
    outp[g * D + j] = fmaxf(acc, 0.f);
}

__global__ void final_k(const float* __restrict__ in, const float* __restrict__ W,
                        const float* __restrict__ b, float* __restrict__ outp) {
    __shared__ float row[D];
    __shared__ float logits[N_CLASSES];
    __shared__ float red[2];
    int g = blockIdx.x, t = threadIdx.x;
    row[t] = in[g * D + t];
    __syncthreads();
    if (t < N_CLASSES) {
        float acc = b[t];
#pragma unroll
        for (int k = 0; k < D; k++) acc = fmaf(row[k], W[k * N_CLASSES + t], acc);
        logits[t] = acc;
    }
    __syncthreads();
    if (t == 0) {
        float m = -1e30f;
        for (int c = 0; c < N_CLASSES; c++) m = fmaxf(m, logits[c]);
        float s = 0.f;
        for (int c = 0; c < N_CLASSES; c++) s += expf(logits[c] - m);
        red[0] = m;
        red[1] = logf(s);
    }
    __syncthreads();
    if (t < N_CLASSES) outp[g * N_CLASSES + t] = logits[t] - red[0] - red[1];
}

// ---------------- launch --------------------------------------------------------
extern "C" void kernel_launch(void* const* d_in, const int* in_sizes, int n_in,
                              void* d_out, int out_size) {
    const float* x    = (const float*)d_in[0];
    const float* gw1  = (const float*)d_in[1];
    const float* gb1  = (const float*)d_in[2];
    const float* gw2  = (const float*)d_in[3];
    const float* gb2  = (const float*)d_in[4];
    const float* gnw  = (const float*)d_in[5];
    const float* gnb  = (const float*)d_in[6];
    const float* gns  = (const float*)d_in[7];
    const float* fw1  = (const float*)d_in[8];
    const float* fb1  = (const float*)d_in[9];
    const float* fw2  = (const float*)d_in[10];
    const float* fb2  = (const float*)d_in[11];
    const float* fw3  = (const float*)d_in[12];
    const float* fb3  = (const float*)d_in[13];
    const int*   edge_raw  = (const int*)d_in[14];
    const int*   batch_raw = (const int*)d_in[15];
    float* out = (float*)d_out;

    float *A, *B, *C, *STATS, *CNTF, *GSUM, *M1, *M2;
    int *CNT, *EDGE, *BATCH, *FLAG;
    int *INDEG, *ROWPTR, *CURSOR, *COL, *BSUM, *BOFF;
    cudaGetSymbolAddress((void**)&A, g_A);
    cudaGetSymbolAddress((void**)&B, g_B);
    cudaGetSymbolAddress((void**)&C, g_C);
    cudaGetSymbolAddress((void**)&STATS, g_stats);
    cudaGetSymbolAddress((void**)&CNT, g_cnt);
    cudaGetSymbolAddress((void**)&CNTF, g_cntf);
    cudaGetSymbolAddress((void**)&GSUM, g_gsum);
    cudaGetSymbolAddress((void**)&M1, g_m1);
    cudaGetSymbolAddress((void**)&M2, g_m2);
    cudaGetSymbolAddress((void**)&EDGE, g_edge);
    cudaGetSymbolAddress((void**)&BATCH, g_batch);
    cudaGetSymbolAddress((void**)&FLAG, g_is64);
    cudaGetSymbolAddress((void**)&INDEG, g_indeg);
    cudaGetSymbolAddress((void**)&ROWPTR, g_rowptr);
    cudaGetSymbolAddress((void**)&CURSOR, g_cursor);
    cudaGetSymbolAddress((void**)&COL, g_col);
    cudaGetSymbolAddress((void**)&BSUM, g_blocksum);
    cudaGetSymbolAddress((void**)&BOFF, g_blockoff);

    const int stat4 = 2 * N_GRAPHS * D / 4;
    const int gsum4 = N_GRAPHS * D / 4;
    const int seg_blocks = (N_NODES + SEG_ROWS - 1) / SEG_ROWS;
    const int gemm_blocks = (N_NODES + BM - 1) / BM;
    const int gather_blocks = (N_NODES * 32 + 255) / 256;
    const int norm_grid = (N_NODES * D + 255) / 256;
    const int egrid = (N_EDGES + 255) / 256;
    const int ngrid = (N_NODES + 255) / 256;

    // canonicalize index dtypes
    detect_k<<<1, 1>>>(edge_raw, FLAG);
    conv_k<<<(2 * N_EDGES + 255) / 256, 256>>>(edge_raw, EDGE, 2 * N_EDGES, FLAG);
    conv_k<<<ngrid, 256>>>(batch_raw, BATCH, N_NODES, FLAG);

    // CSR build (per replay — allocation-free, deterministic workload)
    zero_int_k<<<ngrid, 256>>>(INDEG, N_NODES);
    hist_k<<<egrid, 256>>>(EDGE, INDEG);
    scan1_k<<<SCAN_NBLK, SCAN_BLK>>>(INDEG, ROWPTR, BSUM);
    scan2_k<<<1, 32>>>(BSUM, BOFF, ROWPTR);
    scan3_k<<<ngrid, 256>>>(ROWPTR, CURSOR, BOFF);
    fill_k<<<egrid, 256>>>(EDGE, CURSOR, COL);

    // graph counts
    zero_int_k<<<1, N_GRAPHS>>>(CNT, N_GRAPHS);
    count_k<<<ngrid, 256>>>(BATCH, CNT);
    cntf_k<<<1, N_GRAPHS>>>(CNT, CNTF);

    const float* hin = x;  // layer-1 input read straight from the harness buffer
    for (int l = 0; l < L_LAYERS; l++) {
        const float* w1 = gw1 + l * D * D;
        const float* b1 = gb1 + l * D;
        const float* w2 = gw2 + l * D * D;
        const float* b2 = gb2 + l * D;
        const float* nw = gnw + l * D;
        const float* nb = gnb + l * D;
        const float* ns = gns + l * D;

        gather_k<<<gather_blocks, 256>>>(hin, B, ROWPTR, COL);
        gemm_relu_k<<<gemm_blocks, 256>>>(B, w1, b1, C);
        gemm_relu_k<<<gemm_blocks, 256>>>(C, w2, b2, A);
        zero4_k<<<(stat4 + 255) / 256, 256>>>(STATS, stat4);
        seg_stats_k<<<seg_blocks, D>>>(A, BATCH, STATS);
        norm_k<<<norm_grid, 256>>>(A, BATCH, STATS, CNTF, nw, nb, ns);
        hin = A;
    }

    // readout + MLP head
    zero4_k<<<(gsum4 + 255) / 256, 256>>>(GSUM, gsum4);
    seg_sum_k<<<seg_blocks, D>>>(A, BATCH, GSUM);
    mlp_relu_k<<<N_GRAPHS, D>>>(GSUM, fw1, fb1, M1);
    mlp_relu_k<<<N_GRAPHS, D>>>(M1, fw2, fb2, M2);
    final_k<<<N_GRAPHS, D>>>(M2, fw3, fb3, out);
}

// round 6
// speedup vs baseline: 1.7695x; 1.1853x over previous
#include <cuda_runtime.h>
#include <cuda_bf16.h>
#include <cstdint>

#define N_NODES 50000
#define N_EDGES 800000
#define N_GRAPHS 128
#define D 128
#define L_LAYERS 4
#define N_CLASSES 10
#define GN_EPS 1e-5f

#define SCAN_BLK 1024
#define SCAN_NBLK ((N_NODES + SCAN_BLK - 1) / SCAN_BLK)

#define LDT 136  // padded smem row stride in bf16 elements (128 + 8)

// ---------------- device scratch ----------------------------------------------
__device__ float g_A[N_NODES * D];          // h (layer output)
__device__ float g_B[N_NODES * D];          // h + agg (GIN input)
__device__ float g_C[N_NODES * D];          // GEMM1 output
__device__ float g_stats[2 * N_GRAPHS * D]; // [SUM | SUMSQ]
__device__ int   g_cnt[N_GRAPHS];
__device__ float g_cntf[N_GRAPHS];
__device__ float g_gsum[N_GRAPHS * D];
__device__ float g_m1[N_GRAPHS * D];
__device__ float g_m2[N_GRAPHS * D];
__device__ int   g_edge[2 * N_EDGES];
__device__ int   g_batch[N_NODES];
__device__ int   g_is64;
// CSR
__device__ int   g_indeg[N_NODES];
__device__ int   g_rowptr[N_NODES + 1];
__device__ int   g_cursor[N_NODES];
__device__ int   g_col[N_EDGES];
__device__ int   g_blocksum[SCAN_NBLK];
__device__ int   g_blockoff[SCAN_NBLK];
// prepped weights: 8 matrices x {hi,lo} x [N=128][K=128] bf16 row-major (W^T split)
__device__ __align__(16) __nv_bfloat16 g_wprep[8 * 2 * D * D];

// ---------------- helpers -------------------------------------------------------
__device__ __forceinline__ uint32_t pack_bf16(__nv_bfloat16 a, __nv_bfloat16 b) {
    __nv_bfloat162 t;
    t.x = a; t.y = b;
    return *reinterpret_cast<uint32_t*>(&t);
}

__device__ __forceinline__ void mma16816(float* c, const uint32_t* a, const uint32_t* b) {
    asm volatile(
        "mma.sync.aligned.m16n8k16.row.col.f32.bf16.bf16.f32 "
        "{%0,%1,%2,%3}, {%4,%5,%6,%7}, {%8,%9}, {%0,%1,%2,%3};\n"
        : "+f"(c[0]), "+f"(c[1]), "+f"(c[2]), "+f"(c[3])
        : "r"(a[0]), "r"(a[1]), "r"(a[2]), "r"(a[3]), "r"(b[0]), "r"(b[1]));
}

// ---------------- dtype detection + index conversion --------------------------
__global__ void detect_k(const int* __restrict__ raw, int* __restrict__ flag) {
    int all0 = 1;
    for (int i = 1; i < 64; i += 2)
        if (raw[i] != 0) all0 = 0;
    *flag = all0;
}

__global__ void conv_k(const int* __restrict__ raw, int* __restrict__ dst, int n,
                       const int* __restrict__ flag) {
    int i = blockIdx.x * blockDim.x + threadIdx.x;
    if (i < n) dst[i] = (*flag) ? raw[2 * i] : raw[i];
}

// ---------------- tiny utilities ----------------------------------------------
__global__ void zero4_k(float* __restrict__ d, int n4) {
    int i = blockIdx.x * blockDim.x + threadIdx.x;
    if (i < n4) reinterpret_cast<float4*>(d)[i] = make_float4(0.f, 0.f, 0.f, 0.f);
}

__global__ void zero_int_k(int* __restrict__ d, int n) {
    int i = blockIdx.x * blockDim.x + threadIdx.x;
    if (i < n) d[i] = 0;
}

// ---------------- graph counts -------------------------------------------------
__global__ void count_k(const int* __restrict__ batch, int* __restrict__ cnt) {
    __shared__ int bins[N_GRAPHS];
    if (threadIdx.x < N_GRAPHS) bins[threadIdx.x] = 0;
    __syncthreads();
    int i = blockIdx.x * blockDim.x + threadIdx.x;
    if (i < N_NODES) {
        unsigned g = (unsigned)batch[i];
        if (g < N_GRAPHS) atomicAdd(&bins[g], 1);
    }
    __syncthreads();
    if (threadIdx.x < N_GRAPHS) atomicAdd(&cnt[threadIdx.x], bins[threadIdx.x]);
}

__global__ void cntf_k(const int* __restrict__ cnt, float* __restrict__ cntf) {
    int g = threadIdx.x;
    if (g < N_GRAPHS) cntf[g] = fmaxf((float)cnt[g], 1.0f);
}

// ---------------- CSR build ----------------------------------------------------
__global__ void hist_k(const int* __restrict__ ei, int* __restrict__ indeg) {
    int e = blockIdx.x * blockDim.x + threadIdx.x;
    if (e >= N_EDGES) return;
    unsigned dst = (unsigned)ei[N_EDGES + e];
    if (dst < N_NODES) atomicAdd(&indeg[dst], 1);
}

__global__ void scan1_k(const int* __restrict__ indeg, int* __restrict__ rowptr,
                        int* __restrict__ blocksum) {
    __shared__ int s[SCAN_BLK];
    int t = threadIdx.x;
    int i = blockIdx.x * SCAN_BLK + t;
    int v = (i < N_NODES) ? indeg[i] : 0;
    s[t] = v;
    __syncthreads();
#pragma unroll
    for (int off = 1; off < SCAN_BLK; off <<= 1) {
        int tmp = (t >= off) ? s[t - off] : 0;
        __syncthreads();
        s[t] += tmp;
        __syncthreads();
    }
    if (i < N_NODES) rowptr[i] = s[t] - v;
    if (t == SCAN_BLK - 1) blocksum[blockIdx.x] = s[t];
}

__global__ void scan2_k(const int* __restrict__ blocksum, int* __restrict__ blockoff,
                        int* __restrict__ rowptr) {
    if (threadIdx.x == 0) {
        int acc = 0;
        for (int b = 0; b < SCAN_NBLK; b++) {
            blockoff[b] = acc;
            acc += blocksum[b];
        }
        rowptr[N_NODES] = acc;
    }
}

__global__ void scan3_k(int* __restrict__ rowptr, int* __restrict__ cursor,
                        const int* __restrict__ blockoff) {
    int i = blockIdx.x * blockDim.x + threadIdx.x;
    if (i < N_NODES) {
        int v = rowptr[i] + blockoff[i / SCAN_BLK];
        rowptr[i] = v;
        cursor[i] = v;
    }
}

__global__ void fill_k(const int* __restrict__ ei, int* __restrict__ cursor,
                       int* __restrict__ col) {
    int e = blockIdx.x * blockDim.x + threadIdx.x;
    if (e >= N_EDGES) return;
    unsigned src = (unsigned)ei[e];
    unsigned dst = (unsigned)ei[N_EDGES + e];
    if (src >= N_NODES || dst >= N_NODES) return;
    int pos = atomicAdd(&cursor[dst], 1);
    col[pos] = (int)src;
}

// ---------------- gather: B[i] = h[i] + sum_{j in N_in(i)} h[j] ---------------
__global__ void __launch_bounds__(256)
gather_k(const float* __restrict__ h, float* __restrict__ B,
         const int* __restrict__ rowptr, const int* __restrict__ col) {
    int gid = (blockIdx.x * blockDim.x + threadIdx.x) >> 5;
    int lane = threadIdx.x & 31;
    if (gid >= N_NODES) return;
    int p0 = rowptr[gid], p1 = rowptr[gid + 1];
    float4 acc = *reinterpret_cast<const float4*>(&h[gid * D + lane * 4]);
    int p = p0;
    for (; p + 1 < p1; p += 2) {
        int s0 = __ldg(&col[p]);
        int s1 = __ldg(&col[p + 1]);
        float4 v0 = *reinterpret_cast<const float4*>(&h[s0 * D + lane * 4]);
        float4 v1 = *reinterpret_cast<const float4*>(&h[s1 * D + lane * 4]);
        acc.x += v0.x + v1.x;
        acc.y += v0.y + v1.y;
        acc.z += v0.z + v1.z;
        acc.w += v0.w + v1.w;
    }
    if (p < p1) {
        int s0 = __ldg(&col[p]);
        float4 v0 = *reinterpret_cast<const float4*>(&h[s0 * D + lane * 4]);
        acc.x += v0.x; acc.y += v0.y; acc.z += v0.z; acc.w += v0.w;
    }
    *reinterpret_cast<float4*>(&B[gid * D + lane * 4]) = acc;
}

// ---------------- weight prep: W[K,N] -> split bf16 W^T [N][K] row-major ------
__global__ void prep_w_k(const float* __restrict__ gw1, const float* __restrict__ gw2) {
    int w = blockIdx.x;  // 0..7: 0-3 = W1[l], 4-7 = W2[l]
    const float* W = (w < 4) ? (gw1 + w * D * D) : (gw2 + (w - 4) * D * D);
    __nv_bfloat16* hi = g_wprep + (size_t)(w * 2 + 0) * D * D;
    __nv_bfloat16* lo = g_wprep + (size_t)(w * 2 + 1) * D * D;
    for (int idx = threadIdx.x; idx < D * D; idx += blockDim.x) {
        int n = idx >> 7;       // output feature (B^T row)
        int k = idx & 127;      // input feature (B^T col)
        float x = W[k * D + n];
        __nv_bfloat16 h = __float2bfloat16_rn(x);
        float r = x - __bfloat162float(h);
        hi[n * D + k] = h;
        lo[n * D + k] = __float2bfloat16_rn(r);
    }
}

// ---------------- bf16 MMA GEMM: out = relu(A[M,128] @ W + b), split-bf16 -----
// 128x128 CTA tile, 8 warps = 4(M) x 2(N); warp tile 32x64.
// D = Ahi*Bhi + Ahi*Blo + Alo*Bhi, fp32 accumulate (mma.sync m16n8k16).
#define GEMM_SMEM (4 * 128 * LDT * 2)
__global__ void __launch_bounds__(256, 1)
gemm_mma_k(const float* __restrict__ A, const __nv_bfloat16* __restrict__ Wp,
           const float* __restrict__ bias, float* __restrict__ outp) {
    extern __shared__ __nv_bfloat16 sm[];
    __nv_bfloat16* sBhi = sm;
    __nv_bfloat16* sBlo = sm + 128 * LDT;
    __nv_bfloat16* sAhi = sm + 2 * 128 * LDT;
    __nv_bfloat16* sAlo = sm + 3 * 128 * LDT;

    int tid = threadIdx.x;
    int wid = tid >> 5;
    int lid = tid & 31;
    int g = lid >> 2;        // 0..7
    int t = lid & 3;         // 0..3
    int wm = wid >> 1;       // 0..3 : M band (32 rows)
    int wn = wid & 1;        // 0..1 : N band (64 cols)
    int mbase = blockIdx.x * 128;

    // ---- load prepped weights (hi||lo, 64KB contiguous) into padded smem ----
    {
        const uint4* wsrc = reinterpret_cast<const uint4*>(Wp);
#pragma unroll 4
        for (int i = tid; i < 4096; i += 256) {
            uint4 v = wsrc[i];
            int m = i & 2047;          // uint4 index within one 128x128 matrix
            int row = m >> 4;          // 16 uint4 (128 bf16) per row
            int c8 = (m & 15) * 8;     // bf16 col
            __nv_bfloat16* dst = (i < 2048) ? sBhi : sBlo;
            *reinterpret_cast<uint4*>(&dst[row * LDT + c8]) = v;
        }
    }

    // ---- load + split-convert A tile (row = tid/2, 64 cols per thread) ----
    {
        int row = tid >> 1;
        int half = (tid & 1) * 64;
        int grow = mbase + row;
#pragma unroll
        for (int j = 0; j < 8; j++) {
            float4 x0, x1;
            if (grow < N_NODES) {
                x0 = *reinterpret_cast<const float4*>(&A[(size_t)grow * D + half + j * 8]);
                x1 = *reinterpret_cast<const float4*>(&A[(size_t)grow * D + half + j * 8 + 4]);
            } else {
                x0 = make_float4(0.f, 0.f, 0.f, 0.f);
                x1 = x0;
            }
            float xs[8] = {x0.x, x0.y, x0.z, x0.w, x1.x, x1.y, x1.z, x1.w};
            uint32_t hu[4], lu[4];
#pragma unroll
            for (int q = 0; q < 4; q++) {
                __nv_bfloat16 h0 = __float2bfloat16_rn(xs[2 * q]);
                __nv_bfloat16 h1 = __float2bfloat16_rn(xs[2 * q + 1]);
                float r0 = xs[2 * q] - __bfloat162float(h0);
                float r1 = xs[2 * q + 1] - __bfloat162float(h1);
                hu[q] = pack_bf16(h0, h1);
                lu[q] = pack_bf16(__float2bfloat16_rn(r0), __float2bfloat16_rn(r1));
            }
            int off = row * LDT + half + j * 8;
            *reinterpret_cast<uint4*>(&sAhi[off]) = make_uint4(hu[0], hu[1], hu[2], hu[3]);
            *reinterpret_cast<uint4*>(&sAlo[off]) = make_uint4(lu[0], lu[1], lu[2], lu[3]);
        }
    }
    __syncthreads();

    // ---- MMA mainloop ----
    float acc[2][8][4];
#pragma unroll
    for (int mi = 0; mi < 2; mi++)
#pragma unroll
        for (int ni = 0; ni < 8; ni++)
#pragma unroll
            for (int q = 0; q < 4; q++) acc[mi][ni][q] = 0.f;

#pragma unroll
    for (int ks = 0; ks < 8; ks++) {
        int kb = ks * 16 + t * 2;
        uint32_t ah[2][4], al[2][4];
#pragma unroll
        for (int mi = 0; mi < 2; mi++) {
            int r0 = wm * 32 + mi * 16;
            ah[mi][0] = *reinterpret_cast<const uint32_t*>(&sAhi[(r0 + g) * LDT + kb]);
            ah[mi][1] = *reinterpret_cast<const uint32_t*>(&sAhi[(r0 + g + 8) * LDT + kb]);
            ah[mi][2] = *reinterpret_cast<const uint32_t*>(&sAhi[(r0 + g) * LDT + kb + 8]);
            ah[mi][3] = *reinterpret_cast<const uint32_t*>(&sAhi[(r0 + g + 8) * LDT + kb + 8]);
            al[mi][0] = *reinterpret_cast<const uint32_t*>(&sAlo[(r0 + g) * LDT + kb]);
            al[mi][1] = *reinterpret_cast<const uint32_t*>(&sAlo[(r0 + g + 8) * LDT + kb]);
            al[mi][2] = *reinterpret_cast<const uint32_t*>(&sAlo[(r0 + g) * LDT + kb + 8]);
            al[mi][3] = *reinterpret_cast<const uint32_t*>(&sAlo[(r0 + g + 8) * LDT + kb + 8]);
        }
        uint32_t bh[8][2], bl[8][2];
#pragma unroll
        for (int ni = 0; ni < 8; ni++) {
            int n0 = wn * 64 + ni * 8;
            bh[ni][0] = *reinterpret_cast<const uint32_t*>(&sBhi[(n0 + g) * LDT + kb]);
            bh[ni][1] = *reinterpret_cast<const uint32_t*>(&sBhi[(n0 + g) * LDT + kb + 8]);
            bl[ni][0] = *reinterpret_cast<const uint32_t*>(&sBlo[(n0 + g) * LDT + kb]);
            bl[ni][1] = *reinterpret_cast<const uint32_t*>(&sBlo[(n0 + g) * LDT + kb + 8]);
        }
#pragma unroll
        for (int mi = 0; mi < 2; mi++) {
#pragma unroll
            for (int ni = 0; ni < 8; ni++) {
                mma16816(acc[mi][ni], ah[mi], bh[ni]);
                mma16816(acc[mi][ni], ah[mi], bl[ni]);
                mma16816(acc[mi][ni], al[mi], bh[ni]);
            }
        }
    }

    // ---- epilogue: bias + relu, direct gmem float2 stores ----
#pragma unroll
    for (int mi = 0; mi < 2; mi++) {
        int r0 = mbase + wm * 32 + mi * 16 + g;
#pragma unroll
        for (int ni = 0; ni < 8; ni++) {
            int c0 = wn * 64 + ni * 8 + t * 2;
            float b0 = __ldg(&bias[c0]);
            float b1 = __ldg(&bias[c0 + 1]);
            if (r0 < N_NODES) {
                float2 v;
                v.x = fmaxf(acc[mi][ni][0] + b0, 0.f);
                v.y = fmaxf(acc[mi][ni][1] + b1, 0.f);
                *reinterpret_cast<float2*>(&outp[(size_t)r0 * D + c0]) = v;
            }
            if (r0 + 8 < N_NODES) {
                float2 v;
                v.x = fmaxf(acc[mi][ni][2] + b0, 0.f);
                v.y = fmaxf(acc[mi][ni][3] + b1, 0.f);
                *reinterpret_cast<float2*>(&outp[(size_t)(r0 + 8) * D + c0]) = v;
            }
        }
    }
}

// ---------------- fused segment stats: SUM(h) and SUM(h^2) --------------------
#define SEG_ROWS 256
__global__ void seg_stats_k(const float* __restrict__ h, const int* __restrict__ batch,
                            float* __restrict__ stats) {
    float* SUM = stats;
    float* SQ = stats + N_GRAPHS * D;
    int f = threadIdx.x;
    int r0 = blockIdx.x * SEG_ROWS;
    if (r0 >= N_NODES) return;
    int r1 = min(r0 + SEG_ROWS, N_NODES);
    int gcur = batch[r0] & (N_GRAPHS - 1);
    float s = 0.f, q = 0.f;
    for (int r = r0; r < r1; r++) {
        int g = batch[r] & (N_GRAPHS - 1);
        if (g != gcur) {
            atomicAdd(&SUM[gcur * D + f], s);
            atomicAdd(&SQ[gcur * D + f], q);
            s = 0.f; q = 0.f;
            gcur = g;
        }
        float v = h[r * D + f];
        s += v;
        q = fmaf(v, v, q);
    }
    atomicAdd(&SUM[gcur * D + f], s);
    atomicAdd(&SQ[gcur * D + f], q);
}

__global__ void norm_k(float* __restrict__ h, const int* __restrict__ batch,
                       const float* __restrict__ stats, const float* __restrict__ cntf,
                       const float* __restrict__ weight, const float* __restrict__ bias,
                       const float* __restrict__ scale) {
    const float* SUM = stats;
    const float* SQ = stats + N_GRAPHS * D;
    int idx = blockIdx.x * blockDim.x + threadIdx.x;
    if (idx >= N_NODES * D) return;
    int r = idx >> 7;
    int f = idx & 127;
    int g = batch[r] & (N_GRAPHS - 1);
    float c = cntf[g];
    float sc = scale[f];
    float mean = SUM[g * D + f] / c;
    float q = SQ[g * D + f] / c;
    float var = q - mean * mean * sc * (2.f - sc);
    var = fmaxf(var, 0.f);
    float o = weight[f] * (h[idx] - mean * sc) * rsqrtf(var + GN_EPS) + bias[f];
    h[idx] = fmaxf(o, 0.f);
}

// ---------------- readout segment sum ------------------------------------------
__global__ void seg_sum_k(const float* __restrict__ h, const int* __restrict__ batch,
                          float* __restrict__ out) {
    int f = threadIdx.x;
    int r0 = blockIdx.x * SEG_ROWS;
    if (r0 >= N_NODES) return;
    int r1 = min(r0 + SEG_ROWS, N_NODES);
    int gcur = batch[r0] & (N_GRAPHS - 1);
    float acc = 0.f;
    for (int r = r0; r < r1; r++) {
        int g = batch[r] & (N_GRAPHS - 1);
        if (g != gcur) {
            atomicAdd(&out[gcur * D + f], acc);
            acc = 0.f;
            gcur = g;
        }
        acc += h[r * D + f];
    }
    atomicAdd(&out[gcur * D + f], acc);
}

// ---------------- final MLP -----------------------------------------------------
__global__ void mlp_relu_k(const float* __restrict__ in, const float* __restrict__ W,
                           const float* __restrict__ b, float* __restrict__ outp) {
    __shared__ float row[D];
    int g = blockIdx.x, j = threadIdx.x;
    row[j] = in[g * D + j];
    __syncthreads();
    float acc = b[j];
#pragma unroll
    for (int k = 0; k < D; k++) acc = fmaf(row[k], W[k * D + j], acc);
    outp[g * D + j] = fmaxf(acc, 0.f);
}

__global__ void final_k(const float* __restrict__ in, const float* __restrict__ W,
                        const float* __restrict__ b, float* __restrict__ outp) {
    __shared__ float row[D];
    __shared__ float logits[N_CLASSES];
    __shared__ float red[2];
    int g = blockIdx.x, t = threadIdx.x;
    row[t] = in[g * D + t];
    __syncthreads();
    if (t < N_CLASSES) {
        float acc = b[t];
#pragma unroll
        for (int k = 0; k < D; k++) acc = fmaf(row[k], W[k * N_CLASSES + t], acc);
        logits[t] = acc;
    }
    __syncthreads();
    if (t == 0) {
        float m = -1e30f;
        for (int c = 0; c < N_CLASSES; c++) m = fmaxf(m, logits[c]);
        float s = 0.f;
        for (int c = 0; c < N_CLASSES; c++) s += expf(logits[c] - m);
        red[0] = m;
        red[1] = logf(s);
    }
    __syncthreads();
    if (t < N_CLASSES) outp[g * N_CLASSES + t] = logits[t] - red[0] - red[1];
}

// ---------------- launch --------------------------------------------------------
extern "C" void kernel_launch(void* const* d_in, const int* in_sizes, int n_in,
                              void* d_out, int out_size) {
    const float* x    = (const float*)d_in[0];
    const float* gw1  = (const float*)d_in[1];
    const float* gb1  = (const float*)d_in[2];
    const float* gw2  = (const float*)d_in[3];
    const float* gb2  = (const float*)d_in[4];
    const float* gnw  = (const float*)d_in[5];
    const float* gnb  = (const float*)d_in[6];
    const float* gns  = (const float*)d_in[7];
    const float* fw1  = (const float*)d_in[8];
    const float* fb1  = (const float*)d_in[9];
    const float* fw2  = (const float*)d_in[10];
    const float* fb2  = (const float*)d_in[11];
    const float* fw3  = (const float*)d_in[12];
    const float* fb3  = (const float*)d_in[13];
    const int*   edge_raw  = (const int*)d_in[14];
    const int*   batch_raw = (const int*)d_in[15];
    float* out = (float*)d_out;

    float *A, *B, *C, *STATS, *CNTF, *GSUM, *M1, *M2;
    int *CNT, *EDGE, *BATCH, *FLAG;
    int *INDEG, *ROWPTR, *CURSOR, *COL, *BSUM, *BOFF;
    __nv_bfloat16* WPREP;
    cudaGetSymbolAddress((void**)&A, g_A);
    cudaGetSymbolAddress((void**)&B, g_B);
    cudaGetSymbolAddress((void**)&C, g_C);
    cudaGetSymbolAddress((void**)&STATS, g_stats);
    cudaGetSymbolAddress((void**)&CNT, g_cnt);
    cudaGetSymbolAddress((void**)&CNTF, g_cntf);
    cudaGetSymbolAddress((void**)&GSUM, g_gsum);
    cudaGetSymbolAddress((void**)&M1, g_m1);
    cudaGetSymbolAddress((void**)&M2, g_m2);
    cudaGetSymbolAddress((void**)&EDGE, g_edge);
    cudaGetSymbolAddress((void**)&BATCH, g_batch);
    cudaGetSymbolAddress((void**)&FLAG, g_is64);
    cudaGetSymbolAddress((void**)&INDEG, g_indeg);
    cudaGetSymbolAddress((void**)&ROWPTR, g_rowptr);
    cudaGetSymbolAddress((void**)&CURSOR, g_cursor);
    cudaGetSymbolAddress((void**)&COL, g_col);
    cudaGetSymbolAddress((void**)&BSUM, g_blocksum);
    cudaGetSymbolAddress((void**)&BOFF, g_blockoff);
    cudaGetSymbolAddress((void**)&WPREP, g_wprep);

    cudaFuncSetAttribute(gemm_mma_k, cudaFuncAttributeMaxDynamicSharedMemorySize, GEMM_SMEM);

    const int stat4 = 2 * N_GRAPHS * D / 4;
    const int gsum4 = N_GRAPHS * D / 4;
    const int seg_blocks = (N_NODES + SEG_ROWS - 1) / SEG_ROWS;
    const int gemm_blocks = (N_NODES + 127) / 128;
    const int gather_blocks = (N_NODES * 32 + 255) / 256;
    const int norm_grid = (N_NODES * D + 255) / 256;
    const int egrid = (N_EDGES + 255) / 256;
    const int ngrid = (N_NODES + 255) / 256;

    // canonicalize index dtypes
    detect_k<<<1, 1>>>(edge_raw, FLAG);
    conv_k<<<(2 * N_EDGES + 255) / 256, 256>>>(edge_raw, EDGE, 2 * N_EDGES, FLAG);
    conv_k<<<ngrid, 256>>>(batch_raw, BATCH, N_NODES, FLAG);

    // weight prep for bf16 MMA GEMMs
    prep_w_k<<<8, 256>>>(gw1, gw2);

    // CSR build
    zero_int_k<<<ngrid, 256>>>(INDEG, N_NODES);
    hist_k<<<egrid, 256>>>(EDGE, INDEG);
    scan1_k<<<SCAN_NBLK, SCAN_BLK>>>(INDEG, ROWPTR, BSUM);
    scan2_k<<<1, 32>>>(BSUM, BOFF, ROWPTR);
    scan3_k<<<ngrid, 256>>>(ROWPTR, CURSOR, BOFF);
    fill_k<<<egrid, 256>>>(EDGE, CURSOR, COL);

    // graph counts
    zero_int_k<<<1, N_GRAPHS>>>(CNT, N_GRAPHS);
    count_k<<<ngrid, 256>>>(BATCH, CNT);
    cntf_k<<<1, N_GRAPHS>>>(CNT, CNTF);

    const float* hin = x;
    for (int l = 0; l < L_LAYERS; l++) {
        const float* b1 = gb1 + l * D;
        const float* b2 = gb2 + l * D;
        const float* nw = gnw + l * D;
        const float* nb = gnb + l * D;
        const float* ns = gns + l * D;
        const __nv_bfloat16* wp1 = WPREP + (size_t)(2 * l) * D * D;       // W1[l] hi||lo
        const __nv_bfloat16* wp2 = WPREP + (size_t)(2 * (4 + l)) * D * D; // W2[l] hi||lo

        gather_k<<<gather_blocks, 256>>>(hin, B, ROWPTR, COL);
        gemm_mma_k<<<gemm_blocks, 256, GEMM_SMEM>>>(B, wp1, b1, C);
        gemm_mma_k<<<gemm_blocks, 256, GEMM_SMEM>>>(C, wp2, b2, A);
        zero4_k<<<(stat4 + 255) / 256, 256>>>(STATS, stat4);
        seg_stats_k<<<seg_blocks, D>>>(A, BATCH, STATS);
        norm_k<<<norm_grid, 256>>>(A, BATCH, STATS, CNTF, nw, nb, ns);
        hin = A;
    }

    // readout + MLP head
    zero4_k<<<(gsum4 + 255) / 256, 256>>>(GSUM, gsum4);
    seg_sum_k<<<seg_blocks, D>>>(A, BATCH, GSUM);
    mlp_relu_k<<<N_GRAPHS, D>>>(GSUM, fw1, fb1, M1);
    mlp_relu_k<<<N_GRAPHS, D>>>(M1, fw2, fb2, M2);
    final_k<<<N_GRAPHS, D>>>(M2, fw3, fb3, out);
}

// round 7
// speedup vs baseline: 2.4085x; 1.3611x over previous
#include <cuda_runtime.h>
#include <cuda_bf16.h>
#include <cstdint>

#define N_NODES 50000
#define N_EDGES 800000
#define N_GRAPHS 128
#define D 128
#define L_LAYERS 4
#define N_CLASSES 10
#define GN_EPS 1e-5f

#define SCAN_BLK 1024
#define SCAN_NBLK ((N_NODES + SCAN_BLK - 1) / SCAN_BLK)

#define LDT 136   // padded smem row stride in bf16 elements (128 + 8)
#define STP 132   // fp32 stage pitch (16B-aligned float4 rows)

// ---------------- device scratch ----------------------------------------------
__device__ float g_A[N_NODES * D];          // h (layer output)
__device__ float g_B[N_NODES * D];          // h + agg (GIN input)
__device__ float g_stats[2 * N_GRAPHS * D]; // [SUM | SUMSQ]
__device__ int   g_cnt[N_GRAPHS];
__device__ float g_cntf[N_GRAPHS];
__device__ float g_gsum[N_GRAPHS * D];
__device__ float g_m1[N_GRAPHS * D];
__device__ float g_m2[N_GRAPHS * D];
__device__ int   g_edge[2 * N_EDGES];
__device__ int   g_batch[N_NODES];
__device__ int   g_is64;
// CSR
__device__ int   g_indeg[N_NODES];
__device__ int   g_rowptr[N_NODES + 1];
__device__ int   g_cursor[N_NODES];
__device__ int   g_col[N_EDGES];
__device__ int   g_blocksum[SCAN_NBLK];
__device__ int   g_blockoff[SCAN_NBLK];
// prepped weights: 8 matrices x {hi,lo} x [N=128][K=128] bf16 row-major (W^T split)
__device__ __align__(16) __nv_bfloat16 g_wprep[8 * 2 * D * D];

// ---------------- helpers -------------------------------------------------------
__device__ __forceinline__ uint32_t pack_bf16(__nv_bfloat16 a, __nv_bfloat16 b) {
    __nv_bfloat162 t;
    t.x = a; t.y = b;
    return *reinterpret_cast<uint32_t*>(&t);
}

__device__ __forceinline__ void mma16816(float* c, const uint32_t* a, const uint32_t* b) {
    asm volatile(
        "mma.sync.aligned.m16n8k16.row.col.f32.bf16.bf16.f32 "
        "{%0,%1,%2,%3}, {%4,%5,%6,%7}, {%8,%9}, {%0,%1,%2,%3};\n"
        : "+f"(c[0]), "+f"(c[1]), "+f"(c[2]), "+f"(c[3])
        : "r"(a[0]), "r"(a[1]), "r"(a[2]), "r"(a[3]), "r"(b[0]), "r"(b[1]));
}

// split-bf16 MMA mainloop over a resident 128x128 tile pair
__device__ __forceinline__ void mma_loop(const __nv_bfloat16* sAhi, const __nv_bfloat16* sAlo,
                                         const __nv_bfloat16* sBhi, const __nv_bfloat16* sBlo,
                                         int wm, int wn, int g, int t, float acc[2][8][4]) {
#pragma unroll
    for (int ks = 0; ks < 8; ks++) {
        int kb = ks * 16 + t * 2;
        uint32_t ah[2][4], al[2][4];
#pragma unroll
        for (int mi = 0; mi < 2; mi++) {
            int r0 = wm * 32 + mi * 16;
            ah[mi][0] = *reinterpret_cast<const uint32_t*>(&sAhi[(r0 + g) * LDT + kb]);
            ah[mi][1] = *reinterpret_cast<const uint32_t*>(&sAhi[(r0 + g + 8) * LDT + kb]);
            ah[mi][2] = *reinterpret_cast<const uint32_t*>(&sAhi[(r0 + g) * LDT + kb + 8]);
            ah[mi][3] = *reinterpret_cast<const uint32_t*>(&sAhi[(r0 + g + 8) * LDT + kb + 8]);
            al[mi][0] = *reinterpret_cast<const uint32_t*>(&sAlo[(r0 + g) * LDT + kb]);
            al[mi][1] = *reinterpret_cast<const uint32_t*>(&sAlo[(r0 + g + 8) * LDT + kb]);
            al[mi][2] = *reinterpret_cast<const uint32_t*>(&sAlo[(r0 + g) * LDT + kb + 8]);
            al[mi][3] = *reinterpret_cast<const uint32_t*>(&sAlo[(r0 + g + 8) * LDT + kb + 8]);
        }
        uint32_t bh[8][2], bl[8][2];
#pragma unroll
        for (int ni = 0; ni < 8; ni++) {
            int n0 = wn * 64 + ni * 8;
            bh[ni][0] = *reinterpret_cast<const uint32_t*>(&sBhi[(n0 + g) * LDT + kb]);
            bh[ni][1] = *reinterpret_cast<const uint32_t*>(&sBhi[(n0 + g) * LDT + kb + 8]);
            bl[ni][0] = *reinterpret_cast<const uint32_t*>(&sBlo[(n0 + g) * LDT + kb]);
            bl[ni][1] = *reinterpret_cast<const uint32_t*>(&sBlo[(n0 + g) * LDT + kb + 8]);
        }
#pragma unroll
        for (int mi = 0; mi < 2; mi++) {
#pragma unroll
            for (int ni = 0; ni < 8; ni++) {
                mma16816(acc[mi][ni], ah[mi], bh[ni]);
                mma16816(acc[mi][ni], ah[mi], bl[ni]);
                mma16816(acc[mi][ni], al[mi], bh[ni]);
            }
        }
    }
}

// ---------------- dtype detection + index conversion --------------------------
__global__ void detect_k(const int* __restrict__ raw, int* __restrict__ flag) {
    int all0 = 1;
    for (int i = 1; i < 64; i += 2)
        if (raw[i] != 0) all0 = 0;
    *flag = all0;
}

__global__ void conv_k(const int* __restrict__ raw, int* __restrict__ dst, int n,
                       const int* __restrict__ flag) {
    int i = blockIdx.x * blockDim.x + threadIdx.x;
    if (i < n) dst[i] = (*flag) ? raw[2 * i] : raw[i];
}

// ---------------- tiny utilities ----------------------------------------------
__global__ void zero4_k(float* __restrict__ d, int n4) {
    int i = blockIdx.x * blockDim.x + threadIdx.x;
    if (i < n4) reinterpret_cast<float4*>(d)[i] = make_float4(0.f, 0.f, 0.f, 0.f);
}

__global__ void zero_int_k(int* __restrict__ d, int n) {
    int i = blockIdx.x * blockDim.x + threadIdx.x;
    if (i < n) d[i] = 0;
}

// ---------------- graph counts -------------------------------------------------
__global__ void count_k(const int* __restrict__ batch, int* __restrict__ cnt) {
    __shared__ int bins[N_GRAPHS];
    if (threadIdx.x < N_GRAPHS) bins[threadIdx.x] = 0;
    __syncthreads();
    int i = blockIdx.x * blockDim.x + threadIdx.x;
    if (i < N_NODES) {
        unsigned g = (unsigned)batch[i];
        if (g < N_GRAPHS) atomicAdd(&bins[g], 1);
    }
    __syncthreads();
    if (threadIdx.x < N_GRAPHS) atomicAdd(&cnt[threadIdx.x], bins[threadIdx.x]);
}

__global__ void cntf_k(const int* __restrict__ cnt, float* __restrict__ cntf) {
    int g = threadIdx.x;
    if (g < N_GRAPHS) cntf[g] = fmaxf((float)cnt[g], 1.0f);
}

// ---------------- CSR build ----------------------------------------------------
__global__ void hist_k(const int* __restrict__ ei, int* __restrict__ indeg) {
    int e = blockIdx.x * blockDim.x + threadIdx.x;
    if (e >= N_EDGES) return;
    unsigned dst = (unsigned)ei[N_EDGES + e];
    if (dst < N_NODES) atomicAdd(&indeg[dst], 1);
}

__global__ void scan1_k(const int* __restrict__ indeg, int* __restrict__ rowptr,
                        int* __restrict__ blocksum) {
    __shared__ int s[SCAN_BLK];
    int t = threadIdx.x;
    int i = blockIdx.x * SCAN_BLK + t;
    int v = (i < N_NODES) ? indeg[i] : 0;
    s[t] = v;
    __syncthreads();
#pragma unroll
    for (int off = 1; off < SCAN_BLK; off <<= 1) {
        int tmp = (t >= off) ? s[t - off] : 0;
        __syncthreads();
        s[t] += tmp;
        __syncthreads();
    }
    if (i < N_NODES) rowptr[i] = s[t] - v;
    if (t == SCAN_BLK - 1) blocksum[blockIdx.x] = s[t];
}

__global__ void scan2_k(const int* __restrict__ blocksum, int* __restrict__ blockoff,
                        int* __restrict__ rowptr) {
    if (threadIdx.x == 0) {
        int acc = 0;
        for (int b = 0; b < SCAN_NBLK; b++) {
            blockoff[b] = acc;
            acc += blocksum[b];
        }
        rowptr[N_NODES] = acc;
    }
}

__global__ void scan3_k(int* __restrict__ rowptr, int* __restrict__ cursor,
                        const int* __restrict__ blockoff) {
    int i = blockIdx.x * blockDim.x + threadIdx.x;
    if (i < N_NODES) {
        int v = rowptr[i] + blockoff[i / SCAN_BLK];
        rowptr[i] = v;
        cursor[i] = v;
    }
}

__global__ void fill_k(const int* __restrict__ ei, int* __restrict__ cursor,
                       int* __restrict__ col) {
    int e = blockIdx.x * blockDim.x + threadIdx.x;
    if (e >= N_EDGES) return;
    unsigned src = (unsigned)ei[e];
    unsigned dst = (unsigned)ei[N_EDGES + e];
    if (src >= N_NODES || dst >= N_NODES) return;
    int pos = atomicAdd(&cursor[dst], 1);
    col[pos] = (int)src;
}

// ---------------- gather: B[i] = h[i] + sum_{j in N_in(i)} h[j] ---------------
__global__ void __launch_bounds__(256)
gather_k(const float* __restrict__ h, float* __restrict__ B,
         const int* __restrict__ rowptr, const int* __restrict__ col) {
    int gid = (blockIdx.x * blockDim.x + threadIdx.x) >> 5;
    int lane = threadIdx.x & 31;
    if (gid >= N_NODES) return;
    int p0 = rowptr[gid], p1 = rowptr[gid + 1];
    float4 acc = *reinterpret_cast<const float4*>(&h[gid * D + lane * 4]);
    int p = p0;
    for (; p + 1 < p1; p += 2) {
        int s0 = __ldg(&col[p]);
        int s1 = __ldg(&col[p + 1]);
        float4 v0 = *reinterpret_cast<const float4*>(&h[s0 * D + lane * 4]);
        float4 v1 = *reinterpret_cast<const float4*>(&h[s1 * D + lane * 4]);
        acc.x += v0.x + v1.x;
        acc.y += v0.y + v1.y;
        acc.z += v0.z + v1.z;
        acc.w += v0.w + v1.w;
    }
    if (p < p1) {
        int s0 = __ldg(&col[p]);
        float4 v0 = *reinterpret_cast<const float4*>(&h[s0 * D + lane * 4]);
        acc.x += v0.x; acc.y += v0.y; acc.z += v0.z; acc.w += v0.w;
    }
    *reinterpret_cast<float4*>(&B[gid * D + lane * 4]) = acc;
}

// ---------------- weight prep: W[K,N] -> split bf16 W^T [N][K] row-major ------
__global__ void prep_w_k(const float* __restrict__ gw1, const float* __restrict__ gw2) {
    int w = blockIdx.x >> 3;           // 0..7
    int chunk = blockIdx.x & 7;        // 0..7: 2048 elements each
    const float* W = (w < 4) ? (gw1 + w * D * D) : (gw2 + (w - 4) * D * D);
    __nv_bfloat16* hi = g_wprep + (size_t)(w * 2 + 0) * D * D;
    __nv_bfloat16* lo = g_wprep + (size_t)(w * 2 + 1) * D * D;
    for (int idx = chunk * 2048 + threadIdx.x; idx < (chunk + 1) * 2048; idx += blockDim.x) {
        int n = idx >> 7;
        int k = idx & 127;
        float x = W[k * D + n];
        __nv_bfloat16 h = __float2bfloat16_rn(x);
        float r = x - __bfloat162float(h);
        hi[n * D + k] = h;
        lo[n * D + k] = __float2bfloat16_rn(r);
    }
}

// ---------------- fused double GEMM + GraphNorm stats -------------------------
// A_out = relu(relu(B@W1+b1)@W2+b2); also accumulates per-graph SUM/SUMSQ.
#define GEMM_SMEM (4 * 128 * LDT * 2 + 512)
__global__ void __launch_bounds__(256, 1)
gemm_fused_k(const float* __restrict__ Bin,
             const __nv_bfloat16* __restrict__ Wp1, const float* __restrict__ b1,
             const __nv_bfloat16* __restrict__ Wp2, const float* __restrict__ b2,
             float* __restrict__ outp, const int* __restrict__ batch,
             float* __restrict__ stats) {
    extern __shared__ __nv_bfloat16 sm[];
    __nv_bfloat16* sBhi = sm;
    __nv_bfloat16* sBlo = sm + 128 * LDT;
    __nv_bfloat16* sAhi = sm + 2 * 128 * LDT;
    __nv_bfloat16* sAlo = sm + 3 * 128 * LDT;
    float* stage = reinterpret_cast<float*>(sm);                       // 128*STP*4 = 67584 B
    int* gl = reinterpret_cast<int*>((char*)sm + 4 * 128 * LDT * 2);   // 128 ints

    int tid = threadIdx.x;
    int wid = tid >> 5;
    int lid = tid & 31;
    int g = lid >> 2;
    int t = lid & 3;
    int wm = wid >> 1;
    int wn = wid & 1;
    int mbase = blockIdx.x * 128;

    // graph ids for this row block
    if (tid < 128) {
        int grow = mbase + tid;
        gl[tid] = (grow < N_NODES) ? (batch[grow] & (N_GRAPHS - 1)) : -1;
    }

    // ---- phase 0: W1 -> sB, split-convert input tile -> sA ----
    {
        const uint4* wsrc = reinterpret_cast<const uint4*>(Wp1);
#pragma unroll 4
        for (int i = tid; i < 4096; i += 256) {
            uint4 v = wsrc[i];
            int m = i & 2047;
            int row = m >> 4;
            int c8 = (m & 15) * 8;
            __nv_bfloat16* dst = (i < 2048) ? sBhi : sBlo;
            *reinterpret_cast<uint4*>(&dst[row * LDT + c8]) = v;
        }
    }
    {
        int row = tid >> 1;
        int half = (tid & 1) * 64;
        int grow = mbase + row;
#pragma unroll
        for (int j = 0; j < 8; j++) {
            float4 x0, x1;
            if (grow < N_NODES) {
                x0 = *reinterpret_cast<const float4*>(&Bin[(size_t)grow * D + half + j * 8]);
                x1 = *reinterpret_cast<const float4*>(&Bin[(size_t)grow * D + half + j * 8 + 4]);
            } else {
                x0 = make_float4(0.f, 0.f, 0.f, 0.f);
                x1 = x0;
            }
            float xs[8] = {x0.x, x0.y, x0.z, x0.w, x1.x, x1.y, x1.z, x1.w};
            uint32_t hu[4], lu[4];
#pragma unroll
            for (int q = 0; q < 4; q++) {
                __nv_bfloat16 h0 = __float2bfloat16_rn(xs[2 * q]);
                __nv_bfloat16 h1 = __float2bfloat16_rn(xs[2 * q + 1]);
                float r0 = xs[2 * q] - __bfloat162float(h0);
                float r1 = xs[2 * q + 1] - __bfloat162float(h1);
                hu[q] = pack_bf16(h0, h1);
                lu[q] = pack_bf16(__float2bfloat16_rn(r0), __float2bfloat16_rn(r1));
            }
            int off = row * LDT + half + j * 8;
            *reinterpret_cast<uint4*>(&sAhi[off]) = make_uint4(hu[0], hu[1], hu[2], hu[3]);
            *reinterpret_cast<uint4*>(&sAlo[off]) = make_uint4(lu[0], lu[1], lu[2], lu[3]);
        }
    }
    __syncthreads();

    // ---- mainloop 1 ----
    float acc[2][8][4];
#pragma unroll
    for (int mi = 0; mi < 2; mi++)
#pragma unroll
        for (int ni = 0; ni < 8; ni++)
#pragma unroll
            for (int q = 0; q < 4; q++) acc[mi][ni][q] = 0.f;
    mma_loop(sAhi, sAlo, sBhi, sBlo, wm, wn, g, t, acc);
    __syncthreads();

    // ---- phase 2: C = relu(acc+b1) split into sA; W2 -> sB ----
#pragma unroll
    for (int mi = 0; mi < 2; mi++) {
#pragma unroll
        for (int ni = 0; ni < 8; ni++) {
            int c0 = wn * 64 + ni * 8 + t * 2;
            float bb0 = __ldg(&b1[c0]);
            float bb1 = __ldg(&b1[c0 + 1]);
#pragma unroll
            for (int rr = 0; rr < 2; rr++) {
                int row = wm * 32 + mi * 16 + g + rr * 8;
                float v0 = fmaxf(acc[mi][ni][rr * 2 + 0] + bb0, 0.f);
                float v1 = fmaxf(acc[mi][ni][rr * 2 + 1] + bb1, 0.f);
                __nv_bfloat16 h0 = __float2bfloat16_rn(v0);
                __nv_bfloat16 h1 = __float2bfloat16_rn(v1);
                float r0 = v0 - __bfloat162float(h0);
                float r1 = v1 - __bfloat162float(h1);
                *reinterpret_cast<uint32_t*>(&sAhi[row * LDT + c0]) = pack_bf16(h0, h1);
                *reinterpret_cast<uint32_t*>(&sAlo[row * LDT + c0]) =
                    pack_bf16(__float2bfloat16_rn(r0), __float2bfloat16_rn(r1));
            }
        }
    }
    {
        const uint4* wsrc = reinterpret_cast<const uint4*>(Wp2);
#pragma unroll 4
        for (int i = tid; i < 4096; i += 256) {
            uint4 v = wsrc[i];
            int m = i & 2047;
            int row = m >> 4;
            int c8 = (m & 15) * 8;
            __nv_bfloat16* dst = (i < 2048) ? sBhi : sBlo;
            *reinterpret_cast<uint4*>(&dst[row * LDT + c8]) = v;
        }
    }
    __syncthreads();

    // ---- mainloop 2 ----
#pragma unroll
    for (int mi = 0; mi < 2; mi++)
#pragma unroll
        for (int ni = 0; ni < 8; ni++)
#pragma unroll
            for (int q = 0; q < 4; q++) acc[mi][ni][q] = 0.f;
    mma_loop(sAhi, sAlo, sBhi, sBlo, wm, wn, g, t, acc);
    __syncthreads();   // sB/sA dead; stage may overwrite

    // ---- phase 3: stage relu(acc+b2) ----
#pragma unroll
    for (int mi = 0; mi < 2; mi++) {
#pragma unroll
        for (int ni = 0; ni < 8; ni++) {
            int c0 = wn * 64 + ni * 8 + t * 2;
            float bb0 = __ldg(&b2[c0]);
            float bb1 = __ldg(&b2[c0 + 1]);
#pragma unroll
            for (int rr = 0; rr < 2; rr++) {
                int row = wm * 32 + mi * 16 + g + rr * 8;
                stage[row * STP + c0] = fmaxf(acc[mi][ni][rr * 2 + 0] + bb0, 0.f);
                stage[row * STP + c0 + 1] = fmaxf(acc[mi][ni][rr * 2 + 1] + bb1, 0.f);
            }
        }
    }
    __syncthreads();

    // ---- phase 4a: per-graph stats from stage (sorted batch, flush on change) ----
    {
        int col = tid >> 1;
        int rbeg = (tid & 1) * 64;
        int gcur = gl[rbeg];
        float s = 0.f, q = 0.f;
        if (gcur >= 0) {
            for (int r = rbeg; r < rbeg + 64; r++) {
                int gg = gl[r];
                if (gg < 0) break;
                if (gg != gcur) {
                    atomicAdd(&stats[gcur * D + col], s);
                    atomicAdd(&stats[N_GRAPHS * D + gcur * D + col], q);
                    s = 0.f; q = 0.f;
                    gcur = gg;
                }
                float v = stage[r * STP + col];
                s += v;
                q = fmaf(v, v, q);
            }
            atomicAdd(&stats[gcur * D + col], s);
            atomicAdd(&stats[N_GRAPHS * D + gcur * D + col], q);
        }
    }

    // ---- phase 4b: coalesced fp32 output ----
    for (int i = tid; i < 4096; i += 256) {
        int row = i >> 5;
        int c4 = (i & 31) * 4;
        int grow = mbase + row;
        if (grow < N_NODES) {
            float4 v = *reinterpret_cast<const float4*>(&stage[row * STP + c4]);
            *reinterpret_cast<float4*>(&outp[(size_t)grow * D + c4]) = v;
        }
    }
}

// ---------------- norm + relu, in place -----------------------------------------
__global__ void norm_k(float* __restrict__ h, const int* __restrict__ batch,
                       const float* __restrict__ stats, const float* __restrict__ cntf,
                       const float* __restrict__ weight, const float* __restrict__ bias,
                       const float* __restrict__ scale) {
    const float* SUM = stats;
    const float* SQ = stats + N_GRAPHS * D;
    int idx = blockIdx.x * blockDim.x + threadIdx.x;
    if (idx >= N_NODES * D) return;
    int r = idx >> 7;
    int f = idx & 127;
    int g = batch[r] & (N_GRAPHS - 1);
    float c = cntf[g];
    float sc = scale[f];
    float mean = SUM[g * D + f] / c;
    float q = SQ[g * D + f] / c;
    float var = q - mean * mean * sc * (2.f - sc);
    var = fmaxf(var, 0.f);
    float o = weight[f] * (h[idx] - mean * sc) * rsqrtf(var + GN_EPS) + bias[f];
    h[idx] = fmaxf(o, 0.f);
}

// ---------------- readout segment sum ------------------------------------------
#define SEG_ROWS 256
__global__ void seg_sum_k(const float* __restrict__ h, const int* __restrict__ batch,
                          float* __restrict__ out) {
    int f = threadIdx.x;
    int r0 = blockIdx.x * SEG_ROWS;
    if (r0 >= N_NODES) return;
    int r1 = min(r0 + SEG_ROWS, N_NODES);
    int gcur = batch[r0] & (N_GRAPHS - 1);
    float acc = 0.f;
    for (int r = r0; r < r1; r++) {
        int g = batch[r] & (N_GRAPHS - 1);
        if (g != gcur) {
            atomicAdd(&out[gcur * D + f], acc);
            acc = 0.f;
            gcur = g;
        }
        acc += h[r * D + f];
    }
    atomicAdd(&out[gcur * D + f], acc);
}

// ---------------- final MLP -----------------------------------------------------
__global__ void mlp_relu_k(const float* __restrict__ in, const float* __restrict__ W,
                           const float* __restrict__ b, float* __restrict__ outp) {
    __shared__ float row[D];
    int g = blockIdx.x, j = threadIdx.x;
    row[j] = in[g * D + j];
    __syncthreads();
    float acc = b[j];
#pragma unroll
    for (int k = 0; k < D; k++) acc = fmaf(row[k], W[k * D + j], acc);
    outp[g * D + j] = fmaxf(acc, 0.f);
}

__global__ void final_k(const float* __restrict__ in, const float* __restrict__ W,
                        const float* __restrict__ b, float* __restrict__ outp) {
    __shared__ float row[D];
    __shared__ float logits[N_CLASSES];
    __shared__ float red[2];
    int g = blockIdx.x, t = threadIdx.x;
    row[t] = in[g * D + t];
    __syncthreads();
    if (t < N_CLASSES) {
        float acc = b[t];
#pragma unroll
        for (int k = 0; k < D; k++) acc = fmaf(row[k], W[k * N_CLASSES + t], acc);
        logits[t] = acc;
    }
    __syncthreads();
    if (t == 0) {
        float m = -1e30f;
        for (int c = 0; c < N_CLASSES; c++) m = fmaxf(m, logits[c]);
        float s = 0.f;
        for (int c = 0; c < N_CLASSES; c++) s += expf(logits[c] - m);
        red[0] = m;
        red[1] = logf(s);
    }
    __syncthreads();
    if (t < N_CLASSES) outp[g * N_CLASSES + t] = logits[t] - red[0] - red[1];
}

// ---------------- launch --------------------------------------------------------
extern "C" void kernel_launch(void* const* d_in, const int* in_sizes, int n_in,
                              void* d_out, int out_size) {
    const float* x    = (const float*)d_in[0];
    const float* gw1  = (const float*)d_in[1];
    const float* gb1  = (const float*)d_in[2];
    const float* gw2  = (const float*)d_in[3];
    const float* gb2  = (const float*)d_in[4];
    const float* gnw  = (const float*)d_in[5];
    const float* gnb  = (const float*)d_in[6];
    const float* gns  = (const float*)d_in[7];
    const float* fw1  = (const float*)d_in[8];
    const float* fb1  = (const float*)d_in[9];
    const float* fw2  = (const float*)d_in[10];
    const float* fb2  = (const float*)d_in[11];
    const float* fw3  = (const float*)d_in[12];
    const float* fb3  = (const float*)d_in[13];
    const int*   edge_raw  = (const int*)d_in[14];
    const int*   batch_raw = (const int*)d_in[15];
    float* out = (float*)d_out;

    float *A, *B, *STATS, *CNTF, *GSUM, *M1, *M2;
    int *CNT, *EDGE, *BATCH, *FLAG;
    int *INDEG, *ROWPTR, *CURSOR, *COL, *BSUM, *BOFF;
    __nv_bfloat16* WPREP;
    cudaGetSymbolAddress((void**)&A, g_A);
    cudaGetSymbolAddress((void**)&B, g_B);
    cudaGetSymbolAddress((void**)&STATS, g_stats);
    cudaGetSymbolAddress((void**)&CNT, g_cnt);
    cudaGetSymbolAddress((void**)&CNTF, g_cntf);
    cudaGetSymbolAddress((void**)&GSUM, g_gsum);
    cudaGetSymbolAddress((void**)&M1, g_m1);
    cudaGetSymbolAddress((void**)&M2, g_m2);
    cudaGetSymbolAddress((void**)&EDGE, g_edge);
    cudaGetSymbolAddress((void**)&BATCH, g_batch);
    cudaGetSymbolAddress((void**)&FLAG, g_is64);
    cudaGetSymbolAddress((void**)&INDEG, g_indeg);
    cudaGetSymbolAddress((void**)&ROWPTR, g_rowptr);
    cudaGetSymbolAddress((void**)&CURSOR, g_cursor);
    cudaGetSymbolAddress((void**)&COL, g_col);
    cudaGetSymbolAddress((void**)&BSUM, g_blocksum);
    cudaGetSymbolAddress((void**)&BOFF, g_blockoff);
    cudaGetSymbolAddress((void**)&WPREP, g_wprep);

    cudaFuncSetAttribute(gemm_fused_k, cudaFuncAttributeMaxDynamicSharedMemorySize, GEMM_SMEM);

    const int stat4 = 2 * N_GRAPHS * D / 4;
    const int gsum4 = N_GRAPHS * D / 4;
    const int seg_blocks = (N_NODES + SEG_ROWS - 1) / SEG_ROWS;
    const int gemm_blocks = (N_NODES + 127) / 128;
    const int gather_blocks = (N_NODES * 32 + 255) / 256;
    const int norm_grid = (N_NODES * D + 255) / 256;
    const int egrid = (N_EDGES + 255) / 256;
    const int ngrid = (N_NODES + 255) / 256;

    // canonicalize index dtypes
    detect_k<<<1, 1>>>(edge_raw, FLAG);
    conv_k<<<(2 * N_EDGES + 255) / 256, 256>>>(edge_raw, EDGE, 2 * N_EDGES, FLAG);
    conv_k<<<ngrid, 256>>>(batch_raw, BATCH, N_NODES, FLAG);

    // weight prep for bf16 MMA GEMMs (64 blocks: full-chip spread)
    prep_w_k<<<64, 256>>>(gw1, gw2);

    // CSR build
    zero_int_k<<<ngrid, 256>>>(INDEG, N_NODES);
    hist_k<<<egrid, 256>>>(EDGE, INDEG);
    scan1_k<<<SCAN_NBLK, SCAN_BLK>>>(INDEG, ROWPTR, BSUM);
    scan2_k<<<1, 32>>>(BSUM, BOFF, ROWPTR);
    scan3_k<<<ngrid, 256>>>(ROWPTR, CURSOR, BOFF);
    fill_k<<<egrid, 256>>>(EDGE, CURSOR, COL);

    // graph counts
    zero_int_k<<<1, N_GRAPHS>>>(CNT, N_GRAPHS);
    count_k<<<ngrid, 256>>>(BATCH, CNT);
    cntf_k<<<1, N_GRAPHS>>>(CNT, CNTF);

    const float* hin = x;
    for (int l = 0; l < L_LAYERS; l++) {
        const float* b1 = gb1 + l * D;
        const float* b2 = gb2 + l * D;
        const float* nw = gnw + l * D;
        const float* nb = gnb + l * D;
        const float* ns = gns + l * D;
        const __nv_bfloat16* wp1 = WPREP + (size_t)(2 * l) * D * D;       // W1[l] hi||lo
        const __nv_bfloat16* wp2 = WPREP + (size_t)(2 * (4 + l)) * D * D; // W2[l] hi||lo

        gather_k<<<gather_blocks, 256>>>(hin, B, ROWPTR, COL);
        zero4_k<<<(stat4 + 255) / 256, 256>>>(STATS, stat4);
        gemm_fused_k<<<gemm_blocks, 256, GEMM_SMEM>>>(B, wp1, b1, wp2, b2, A, BATCH, STATS);
        norm_k<<<norm_grid, 256>>>(A, BATCH, STATS, CNTF, nw, nb, ns);
        hin = A;
    }

    // readout + MLP head
    zero4_k<<<(gsum4 + 255) / 256, 256>>>(GSUM, gsum4);
    seg_sum_k<<<seg_blocks, D>>>(A, BATCH, GSUM);
    mlp_relu_k<<<N_GRAPHS, D>>>(GSUM, fw1, fb1, M1);
    mlp_relu_k<<<N_GRAPHS, D>>>(M1, fw2, fb2, M2);
    final_k<<<N_GRAPHS, D>>>(M2, fw3, fb3, out);
}